// round 3
// baseline (speedup 1.0000x reference)
#include <cuda_runtime.h>
#include <math.h>
#include <stdint.h>

#define B 64
#define R 196
#define L 512
#define K 768
#define NEGF (-2147483647.0f)

// Scratch (no cudaMalloc allowed)
__device__ float g_c[B * R];        // 1 + tanh(image proj)
__device__ float g_q[B * L];        // tanh(seq proj)
__device__ float g_w[B * L];        // q @ V
__device__ float g_S[(size_t)B * R * L]; // softmax probs (pre-scaled by 1/(Z*sqrt(K)))

// ---------------------------------------------------------------------------
// Kernel 1: c[b,r] = 1 + tanh(image_emb[b,r,:] . image_W + image_b)
// ---------------------------------------------------------------------------
__global__ void k_proj_p(const float* __restrict__ img,
                         const float* __restrict__ W,
                         const float* __restrict__ bias) {
    int warp = (blockIdx.x * blockDim.x + threadIdx.x) >> 5;
    int lane = threadIdx.x & 31;
    if (warp >= B * R) return;
    const float* row = img + (size_t)warp * L;
    float s = 0.f;
#pragma unroll
    for (int i = 0; i < L / 32; i++) {
        int j = lane + 32 * i;
        s += row[j] * W[j];
    }
#pragma unroll
    for (int o = 16; o; o >>= 1) s += __shfl_xor_sync(0xffffffffu, s, o);
    if (lane == 0) g_c[warp] = 1.0f + tanhf(s + bias[0]);
}

// ---------------------------------------------------------------------------
// Kernel 2: q[b,l] = tanh(seq_emb[b,l,:] . seq_W + seq_b)
// ---------------------------------------------------------------------------
__global__ void k_proj_q(const float* __restrict__ seq,
                         const float* __restrict__ W,
                         const float* __restrict__ bias) {
    int warp = (blockIdx.x * blockDim.x + threadIdx.x) >> 5;
    int lane = threadIdx.x & 31;
    if (warp >= B * L) return;
    const float* row = seq + (size_t)warp * K;
    float s = 0.f;
#pragma unroll
    for (int i = 0; i < K / 32; i++) {
        int j = lane + 32 * i;
        s += row[j] * W[j];
    }
#pragma unroll
    for (int o = 16; o; o >>= 1) s += __shfl_xor_sync(0xffffffffu, s, o);
    if (lane == 0) g_q[warp] = tanhf(s + bias[0]);
}

// ---------------------------------------------------------------------------
// Kernel 3: w[b,j] = sum_l q[b,l] * V[l,j]
// ---------------------------------------------------------------------------
__global__ void k_wgemv(const float* __restrict__ V) {
    int b = blockIdx.x >> 2;
    int j = ((blockIdx.x & 3) << 7) + threadIdx.x;
    __shared__ float qs[L];
    for (int i = threadIdx.x; i < L; i += 128) qs[i] = g_q[b * L + i];
    __syncthreads();
    float acc = 0.f;
#pragma unroll 8
    for (int l = 0; l < L; l++) acc += qs[l] * V[l * L + j];
    g_w[b * L + j] = acc;
}

// ---------------------------------------------------------------------------
// Kernel 4: masked softmax rows -> g_S (scaled by 1/(Z*sqrt(K)))
// ---------------------------------------------------------------------------
__global__ void k_softmax(const int* __restrict__ mask) {
    int b = blockIdx.x;
    int r = blockIdx.y * 8 + (threadIdx.x >> 5);
    int lane = threadIdx.x & 31;
    __shared__ float ws[L];
    __shared__ int ms[L];
    for (int i = threadIdx.x; i < L; i += 256) {
        ws[i] = g_w[b * L + i];
        ms[i] = mask[b * L + i];
    }
    __syncthreads();
    if (r >= R) return;
    float c = g_c[b * R + r];
    float v[L / 32];
    float m = -INFINITY;
#pragma unroll
    for (int i = 0; i < L / 32; i++) {
        int j = lane + 32 * i;
        v[i] = ms[j] ? c * ws[j] : NEGF;
        m = fmaxf(m, v[i]);
    }
#pragma unroll
    for (int o = 16; o; o >>= 1) m = fmaxf(m, __shfl_xor_sync(0xffffffffu, m, o));
    float z = 0.f;
#pragma unroll
    for (int i = 0; i < L / 32; i++) {
        v[i] = __expf(v[i] - m);
        z += v[i];
    }
#pragma unroll
    for (int o = 16; o; o >>= 1) z += __shfl_xor_sync(0xffffffffu, z, o);
    float inv = 1.0f / (z * 27.712812921102035f); // fold 1/sqrt(768)
    float* Srow = g_S + ((size_t)(b * R + r)) * L;
#pragma unroll
    for (int i = 0; i < L / 32; i++) Srow[lane + 32 * i] = v[i] * inv;
}

// ---------------------------------------------------------------------------
// Kernel 5: out[b] = S[b] (196x512) @ seq_emb[b] (512x768), tf32 tensor cores.
// BM=128, BN=128, BK=32; 8 warps = 4(M) x 2(N); warp tile 32x64.
// Software pipeline: register-staged prefetch of tile k+1 during mma on tile k,
// double-buffered dynamic smem, ONE __syncthreads per K-iteration.
// fp32 -> tf32 via cvt.rna at the regs->smem stage (keeps RNA rounding).
// ---------------------------------------------------------------------------
#define BM 128
#define BN 128
#define BK 32
#define ASTR 36
#define BSTR 136
#define A_TILE (BM * ASTR)   // 4608 words
#define B_TILE (BK * BSTR)   // 4352 words
#define SMEM_WORDS (2 * A_TILE + 2 * B_TILE)
#define SMEM_BYTES (SMEM_WORDS * 4)   // 71680
#define NIT (L / BK)         // 16

__device__ __forceinline__ uint32_t f2tf32(float v) {
    uint32_t r;
    asm("cvt.rna.tf32.f32 %0, %1;" : "=r"(r) : "f"(v));
    return r;
}

__global__ __launch_bounds__(256, 1) void k_gemm_tf32(const float* __restrict__ E,
                                                      float* __restrict__ out) {
    const int b = blockIdx.z;
    const int m0 = blockIdx.y * BM;
    const int n0 = blockIdx.x * BN;
    const float* Sb = g_S + (size_t)b * R * L;
    const float* Eb = E + (size_t)b * L * K;
    float* Ob = out + (size_t)b * R * K;

    extern __shared__ __align__(16) uint32_t smem[];
    uint32_t* As = smem;                 // 2 * A_TILE
    uint32_t* Bs = smem + 2 * A_TILE;    // 2 * B_TILE

    const int tid = threadIdx.x;
    const int wid = tid >> 5;
    const int lane = tid & 31;
    const int warp_m = (wid & 3) * 32;
    const int warp_n = (wid >> 2) * 64;
    const int lq = lane >> 2;   // 0..7
    const int lr = lane & 3;    // 0..3

    // Precomputed per-thread load coordinates
    int a_row[4], a_c4[4], b_row[4], b_c4[4];
#pragma unroll
    for (int i = 0; i < 4; i++) {
        int idx = tid + i * 256;
        a_row[i] = idx >> 3;  a_c4[i] = idx & 7;    // A: 128 rows x 8 float4
        b_row[i] = idx >> 5;  b_c4[i] = idx & 31;   // B: 32 rows x 32 float4
    }

    float acc[2][8][4];
#pragma unroll
    for (int i = 0; i < 2; i++)
#pragma unroll
        for (int j = 0; j < 8; j++)
#pragma unroll
            for (int k = 0; k < 4; k++) acc[i][j][k] = 0.f;

    float4 ar[4], br[4];

    // ---- load tile 0 into regs ----
#pragma unroll
    for (int i = 0; i < 4; i++) {
        int gm = m0 + a_row[i];
        ar[i] = make_float4(0.f, 0.f, 0.f, 0.f);
        if (gm < R) ar[i] = *(const float4*)&Sb[(size_t)gm * L + a_c4[i] * 4];
        br[i] = *(const float4*)&Eb[(size_t)b_row[i] * K + n0 + b_c4[i] * 4];
    }
    // ---- store tile 0 -> buffer 0 ----
#pragma unroll
    for (int i = 0; i < 4; i++) {
        uint32_t* da = &As[a_row[i] * ASTR + a_c4[i] * 4];
        da[0] = f2tf32(ar[i].x); da[1] = f2tf32(ar[i].y);
        da[2] = f2tf32(ar[i].z); da[3] = f2tf32(ar[i].w);
        uint32_t* db = &Bs[b_row[i] * BSTR + b_c4[i] * 4];
        db[0] = f2tf32(br[i].x); db[1] = f2tf32(br[i].y);
        db[2] = f2tf32(br[i].z); db[3] = f2tf32(br[i].w);
    }
    __syncthreads();

    int buf = 0;
    for (int it = 0; it < NIT; it++) {
        // ---- prefetch tile it+1 into regs (LDGs fly over the mma burst) ----
        if (it + 1 < NIT) {
            int k0 = (it + 1) * BK;
#pragma unroll
            for (int i = 0; i < 4; i++) {
                int gm = m0 + a_row[i];
                ar[i] = make_float4(0.f, 0.f, 0.f, 0.f);
                if (gm < R) ar[i] = *(const float4*)&Sb[(size_t)gm * L + k0 + a_c4[i] * 4];
                br[i] = *(const float4*)&Eb[(size_t)(k0 + b_row[i]) * K + n0 + b_c4[i] * 4];
            }
        }

        // ---- mma burst on current buffer ----
        const uint32_t* Ab = As + buf * A_TILE;
        const uint32_t* Bb = Bs + buf * B_TILE;
#pragma unroll
        for (int ks = 0; ks < BK / 8; ks++) {
            uint32_t af[2][4];
#pragma unroll
            for (int mi = 0; mi < 2; mi++) {
                int row = warp_m + mi * 16 + lq;
                int col = ks * 8 + lr;
                af[mi][0] = Ab[row * ASTR + col];
                af[mi][1] = Ab[(row + 8) * ASTR + col];
                af[mi][2] = Ab[row * ASTR + col + 4];
                af[mi][3] = Ab[(row + 8) * ASTR + col + 4];
            }
            uint32_t bf[8][2];
#pragma unroll
            for (int ni = 0; ni < 8; ni++) {
                int col = warp_n + ni * 8 + lq;
                bf[ni][0] = Bb[(ks * 8 + lr) * BSTR + col];
                bf[ni][1] = Bb[(ks * 8 + 4 + lr) * BSTR + col];
            }
#pragma unroll
            for (int mi = 0; mi < 2; mi++)
#pragma unroll
                for (int ni = 0; ni < 8; ni++) {
                    asm volatile(
                        "mma.sync.aligned.m16n8k8.row.col.f32.tf32.tf32.f32 "
                        "{%0,%1,%2,%3}, {%4,%5,%6,%7}, {%8,%9}, {%0,%1,%2,%3};"
                        : "+f"(acc[mi][ni][0]), "+f"(acc[mi][ni][1]),
                          "+f"(acc[mi][ni][2]), "+f"(acc[mi][ni][3])
                        : "r"(af[mi][0]), "r"(af[mi][1]), "r"(af[mi][2]), "r"(af[mi][3]),
                          "r"(bf[ni][0]), "r"(bf[ni][1]));
                }
        }

        // ---- cvt + store prefetched tile into the other buffer ----
        if (it + 1 < NIT) {
            uint32_t* An = As + (buf ^ 1) * A_TILE;
            uint32_t* Bn = Bs + (buf ^ 1) * B_TILE;
#pragma unroll
            for (int i = 0; i < 4; i++) {
                uint32_t* da = &An[a_row[i] * ASTR + a_c4[i] * 4];
                da[0] = f2tf32(ar[i].x); da[1] = f2tf32(ar[i].y);
                da[2] = f2tf32(ar[i].z); da[3] = f2tf32(ar[i].w);
                uint32_t* db = &Bn[b_row[i] * BSTR + b_c4[i] * 4];
                db[0] = f2tf32(br[i].x); db[1] = f2tf32(br[i].y);
                db[2] = f2tf32(br[i].z); db[3] = f2tf32(br[i].w);
            }
        }
        __syncthreads();
        buf ^= 1;
    }

    // ---- Epilogue ----
#pragma unroll
    for (int mi = 0; mi < 2; mi++) {
#pragma unroll
        for (int ni = 0; ni < 8; ni++) {
            int gn = n0 + warp_n + ni * 8 + 2 * lr;
            int gm0 = m0 + warp_m + mi * 16 + lq;
            if (gm0 < R) {
                float2 v = make_float2(acc[mi][ni][0], acc[mi][ni][1]);
                *(float2*)&Ob[(size_t)gm0 * K + gn] = v;
            }
            int gm1 = gm0 + 8;
            if (gm1 < R) {
                float2 v = make_float2(acc[mi][ni][2], acc[mi][ni][3]);
                *(float2*)&Ob[(size_t)gm1 * K + gn] = v;
            }
        }
    }
}

// ---------------------------------------------------------------------------
extern "C" void kernel_launch(void* const* d_in, const int* in_sizes, int n_in,
                              void* d_out, int out_size) {
    const float* image_emb = (const float*)d_in[0]; // [B,R,L]
    const float* seq_emb   = (const float*)d_in[1]; // [B,L,K]
    const int*   mask      = (const int*)d_in[2];   // [B,L]
    const float* image_W   = (const float*)d_in[3]; // [L,1]
    const float* image_b   = (const float*)d_in[4]; // [1]
    const float* seq_W     = (const float*)d_in[5]; // [K,1]
    const float* seq_b     = (const float*)d_in[6]; // [1]
    const float* V_weight  = (const float*)d_in[7]; // [L,L]
    float* out = (float*)d_out;                     // [B,R,K]

    // idempotent, host-side, not a stream op — safe under graph capture
    cudaFuncSetAttribute(k_gemm_tf32, cudaFuncAttributeMaxDynamicSharedMemorySize,
                         SMEM_BYTES);

    k_proj_p<<<(B * R + 7) / 8, 256>>>(image_emb, image_W, image_b);
    k_proj_q<<<(B * L + 7) / 8, 256>>>(seq_emb, seq_W, seq_b);
    k_wgemv<<<B * 4, 128>>>(V_weight);
    k_softmax<<<dim3(B, (R + 7) / 8), 256>>>(mask);
    k_gemm_tf32<<<dim3(K / BN, (R + BM - 1) / BM, B), 256, SMEM_BYTES>>>(seq_emb, out);
}

// round 8
// speedup vs baseline: 1.2464x; 1.2464x over previous
#include <cuda_runtime.h>
#include <cuda_fp16.h>
#include <math.h>
#include <stdint.h>

#define B 64
#define R 196
#define L 512
#define K 768
#define NEGF (-2147483647.0f)

// ---------------------------------------------------------------------------
// Scratch (no cudaMalloc allowed). g_S is fp16 (stored as ushort) with 64 rows
// of slop so GEMM M-padding reads stay in-bounds (zero-initialized).
// ---------------------------------------------------------------------------
__device__ float g_c[B * R];                            // 1 + tanh(image proj)
__device__ float g_q[B * L];                            // tanh(seq proj)
__device__ unsigned short g_S[((size_t)B * R + 64) * L]; // softmax probs, fp16

__device__ __forceinline__ uint32_t pack_f2h(float a, float b) {
    return (uint32_t)__half_as_ushort(__float2half_rn(a)) |
           ((uint32_t)__half_as_ushort(__float2half_rn(b)) << 16);
}

// ---------------------------------------------------------------------------
// Kernel 1 (prep1): fused p- and q-projections, one warp per row.
// ---------------------------------------------------------------------------
__global__ void k_prep1(const float* __restrict__ img, const float* __restrict__ iW,
                        const float* __restrict__ ib, const float* __restrict__ seq,
                        const float* __restrict__ sW, const float* __restrict__ sb2) {
    int gid = (blockIdx.x * blockDim.x + threadIdx.x) >> 5;
    int lane = threadIdx.x & 31;
    if (gid < B * R) {
        const float* row = img + (size_t)gid * L;
        float s = 0.f;
#pragma unroll
        for (int i = 0; i < L / 32; i++) s += row[lane + 32 * i] * iW[lane + 32 * i];
#pragma unroll
        for (int o = 16; o; o >>= 1) s += __shfl_xor_sync(0xffffffffu, s, o);
        if (lane == 0) g_c[gid] = 1.0f + tanhf(s + ib[0]);
    } else {
        int rq = gid - B * R;   // < B*L by grid sizing
        const float* row = seq + (size_t)rq * K;
        float s = 0.f;
#pragma unroll
        for (int i = 0; i < K / 32; i++) s += row[lane + 32 * i] * sW[lane + 32 * i];
#pragma unroll
        for (int o = 16; o; o >>= 1) s += __shfl_xor_sync(0xffffffffu, s, o);
        if (lane == 0) g_q[rq] = tanhf(s + sb2[0]);
    }
}

// ---------------------------------------------------------------------------
// Kernel 2 (prep2): per-batch  w = q @ V  then masked softmax -> g_S (fp16).
// ---------------------------------------------------------------------------
__global__ __launch_bounds__(512) void k_prep2(const int* __restrict__ mask,
                                               const float* __restrict__ V) {
    const int b = blockIdx.x;
    const int t = threadIdx.x;
    __shared__ float qs[L];
    __shared__ float ws[L];
    __shared__ int ms[L];
    qs[t] = g_q[b * L + t];
    ms[t] = mask[b * L + t];
    __syncthreads();
    float acc = 0.f;
#pragma unroll 8
    for (int l = 0; l < L; l++) acc += qs[l] * V[l * L + t];
    ws[t] = acc;
    __syncthreads();
    const int wid = t >> 5;
    const int lane = t & 31;
    for (int r = wid; r < R; r += 16) {
        float c = g_c[b * R + r];
        float v[L / 32];
        float m = -INFINITY;
#pragma unroll
        for (int i = 0; i < L / 32; i++) {
            int j = lane + 32 * i;
            v[i] = ms[j] ? c * ws[j] : NEGF;
            m = fmaxf(m, v[i]);
        }
#pragma unroll
        for (int o = 16; o; o >>= 1) m = fmaxf(m, __shfl_xor_sync(0xffffffffu, m, o));
        float z = 0.f;
#pragma unroll
        for (int i = 0; i < L / 32; i++) {
            v[i] = __expf(v[i] - m);
            z += v[i];
        }
#pragma unroll
        for (int o = 16; o; o >>= 1) z += __shfl_xor_sync(0xffffffffu, z, o);
        float inv = 1.0f / (z * 27.712812921102035f);   // fold 1/sqrt(768)
        unsigned short* Srow = g_S + ((size_t)(b * R + r)) * L;
#pragma unroll
        for (int i = 0; i < L / 32; i++)
            Srow[lane + 32 * i] = __half_as_ushort(__float2half_rn(v[i] * inv));
    }
}

// ---------------------------------------------------------------------------
// Kernel 3: out[b] = S[b] (196x512, fp16) @ seq_emb[b] (512x768, ->fp16)
// mma.sync m16n8k16 f16, fp32 accumulate.
// BM=128, BN=128, BK=32; 8 warps = 4(M) x 2(N); warp tile 32x64.
// A smem [m][k] fp16 pitch 40 halves; B smem [k][n] fp16 pitch 136 halves.
// Double-buffered, register prefetch, 2 CTAs/SM.
// ---------------------------------------------------------------------------
#define BM 128
#define BN 128
#define BK 32
#define APITCH 40    // halves
#define BPITCH 136   // halves
#define NIT (L / BK) // 16

__global__ __launch_bounds__(256, 2) void k_gemm_f16(const float* __restrict__ E,
                                                     float* __restrict__ out) {
    const int b = blockIdx.z;
    const int m0 = blockIdx.y * BM;
    const int n0 = blockIdx.x * BN;
    const unsigned short* Sb = g_S + (size_t)b * R * L;
    const float* Eb = E + (size_t)b * L * K + n0;
    float* Ob = out + (size_t)b * R * K;

    __shared__ __align__(16) unsigned short As[2][BM * APITCH];
    __shared__ __align__(16) unsigned short Bs[2][BK * BPITCH];

    const int t = threadIdx.x;
    const int wid = t >> 5;
    const int lane = t & 31;
    const int warp_m = (wid & 3) * 32;
    const int warp_n = (wid >> 2) * 64;
    const int lq = lane >> 2;   // 0..7
    const int lr = lane & 3;    // 0..3

    // loader coordinates
    const int a_row0 = t >> 2, a_c8 = t & 3;   // A: 128 rows x 4 groups of 8 halves
    const int b_kr0 = t >> 5, b_n4 = t & 31;   // B: 32 k-rows x 32 groups of 4 floats

    float acc[2][8][4];
#pragma unroll
    for (int i = 0; i < 2; i++)
#pragma unroll
        for (int j = 0; j < 8; j++)
#pragma unroll
            for (int k2 = 0; k2 < 4; k2++) acc[i][j][k2] = 0.f;

    uint4 ra[2];
    float4 rb[4];

    // prefetch tile 0 (note m0 in the A row index!)
#pragma unroll
    for (int i = 0; i < 2; i++)
        ra[i] = *(const uint4*)&Sb[(size_t)(m0 + a_row0 + i * 64) * L + a_c8 * 8];
#pragma unroll
    for (int i = 0; i < 4; i++)
        rb[i] = *(const float4*)&Eb[(size_t)(b_kr0 + i * 8) * K + b_n4 * 4];

    int buf = 0;
    for (int it = 0; it < NIT; it++) {
        // store prefetched tile into buf
#pragma unroll
        for (int i = 0; i < 2; i++)
            *(uint4*)&As[buf][(a_row0 + i * 64) * APITCH + a_c8 * 8] = ra[i];
#pragma unroll
        for (int i = 0; i < 4; i++) {
            uint2 pk = make_uint2(pack_f2h(rb[i].x, rb[i].y),
                                  pack_f2h(rb[i].z, rb[i].w));
            *(uint2*)&Bs[buf][(b_kr0 + i * 8) * BPITCH + b_n4 * 4] = pk;
        }
        __syncthreads();

        // prefetch next tile into regs (LDGs fly over the mma burst)
        if (it + 1 < NIT) {
            const int k0 = (it + 1) * BK;
#pragma unroll
            for (int i = 0; i < 2; i++)
                ra[i] = *(const uint4*)&Sb[(size_t)(m0 + a_row0 + i * 64) * L + k0 + a_c8 * 8];
#pragma unroll
            for (int i = 0; i < 4; i++)
                rb[i] = *(const float4*)&Eb[(size_t)(k0 + b_kr0 + i * 8) * K + b_n4 * 4];
        }

        // mma burst on buf: 2 k16-steps
        const unsigned short* Ab = As[buf];
        const unsigned short* Bb = Bs[buf];
#pragma unroll
        for (int ks = 0; ks < 2; ks++) {
            uint32_t af[2][4];
#pragma unroll
            for (int mi = 0; mi < 2; mi++) {
                int row = warp_m + mi * 16 + lq;
                int base = row * APITCH + ks * 16 + 2 * lr;
                af[mi][0] = *(const uint32_t*)&Ab[base];
                af[mi][1] = *(const uint32_t*)&Ab[base + 8 * APITCH];
                af[mi][2] = *(const uint32_t*)&Ab[base + 8];
                af[mi][3] = *(const uint32_t*)&Ab[base + 8 * APITCH + 8];
            }
            uint32_t bf[8][2];
#pragma unroll
            for (int ni = 0; ni < 8; ni++) {
                int n = warp_n + ni * 8 + lq;
                int kk = ks * 16 + 2 * lr;
                uint32_t h0 = Bb[kk * BPITCH + n];
                uint32_t h1 = Bb[(kk + 1) * BPITCH + n];
                uint32_t h2 = Bb[(kk + 8) * BPITCH + n];
                uint32_t h3 = Bb[(kk + 9) * BPITCH + n];
                bf[ni][0] = h0 | (h1 << 16);
                bf[ni][1] = h2 | (h3 << 16);
            }
#pragma unroll
            for (int mi = 0; mi < 2; mi++)
#pragma unroll
                for (int ni = 0; ni < 8; ni++) {
                    asm volatile(
                        "mma.sync.aligned.m16n8k16.row.col.f32.f16.f16.f32 "
                        "{%0,%1,%2,%3}, {%4,%5,%6,%7}, {%8,%9}, {%0,%1,%2,%3};"
                        : "+f"(acc[mi][ni][0]), "+f"(acc[mi][ni][1]),
                          "+f"(acc[mi][ni][2]), "+f"(acc[mi][ni][3])
                        : "r"(af[mi][0]), "r"(af[mi][1]), "r"(af[mi][2]), "r"(af[mi][3]),
                          "r"(bf[ni][0]), "r"(bf[ni][1]));
                }
        }
        __syncthreads();
        buf ^= 1;
    }

    // Epilogue: c0,c1 = (row lq, cols 2lr,2lr+1); c2,c3 = row lq+8
#pragma unroll
    for (int mi = 0; mi < 2; mi++) {
#pragma unroll
        for (int ni = 0; ni < 8; ni++) {
            int gn = n0 + warp_n + ni * 8 + 2 * lr;
            int gm0 = m0 + warp_m + mi * 16 + lq;
            if (gm0 < R) {
                float2 v = make_float2(acc[mi][ni][0], acc[mi][ni][1]);
                *(float2*)&Ob[(size_t)gm0 * K + gn] = v;
            }
            int gm1 = gm0 + 8;
            if (gm1 < R) {
                float2 v = make_float2(acc[mi][ni][2], acc[mi][ni][3]);
                *(float2*)&Ob[(size_t)gm1 * K + gn] = v;
            }
        }
    }
}

// ---------------------------------------------------------------------------
extern "C" void kernel_launch(void* const* d_in, const int* in_sizes, int n_in,
                              void* d_out, int out_size) {
    const float* image_emb = (const float*)d_in[0]; // [B,R,L]
    const float* seq_emb   = (const float*)d_in[1]; // [B,L,K]
    const int*   mask      = (const int*)d_in[2];   // [B,L]
    const float* image_W   = (const float*)d_in[3]; // [L,1]
    const float* image_b   = (const float*)d_in[4]; // [1]
    const float* seq_W     = (const float*)d_in[5]; // [K,1]
    const float* seq_b     = (const float*)d_in[6]; // [1]
    const float* V_weight  = (const float*)d_in[7]; // [L,L]
    float* out = (float*)d_out;                     // [B,R,K]

    // 1) fused projections
    k_prep1<<<(B * R + B * L) / 8, 256>>>(image_emb, image_W, image_b,
                                          seq_emb, seq_W, seq_b);
    // 2) per-batch w + softmax -> fp16 S
    k_prep2<<<B, 512>>>(mask, V_weight);
    // 3) fp16 tensor-core GEMM
    k_gemm_f16<<<dim3(K / BN, (R + BM - 1) / BM, B), 256>>>(seq_emb, out);
}

// round 9
// speedup vs baseline: 1.3798x; 1.1070x over previous
#include <cuda_runtime.h>
#include <cuda_fp16.h>
#include <math.h>
#include <stdint.h>

#define B 64
#define R 196
#define L 512
#define K 768
#define NEGF (-2147483647.0f)

// ---------------------------------------------------------------------------
// Scratch (no cudaMalloc allowed). g_S is fp16 (stored as ushort) with 64 rows
// of slop so GEMM M-padding reads stay in-bounds (zero-initialized).
// ---------------------------------------------------------------------------
__device__ float g_c[B * R];                            // 1 + tanh(image proj)
__device__ float g_q[B * L];                            // tanh(seq proj)
__device__ unsigned short g_S[((size_t)B * R + 64) * L]; // softmax probs, fp16

__device__ __forceinline__ uint32_t pack_f2h(float a, float b) {
    return (uint32_t)__half_as_ushort(__float2half_rn(a)) |
           ((uint32_t)__half_as_ushort(__float2half_rn(b)) << 16);
}
__device__ __forceinline__ uint32_t smem_u32(const void* p) {
    uint32_t a;
    asm("{ .reg .u64 t; cvta.to.shared.u64 t, %1; cvt.u32.u64 %0, t; }"
        : "=r"(a) : "l"(p));
    return a;
}

// ---------------------------------------------------------------------------
// Kernel 1 (prep1): fused p- and q-projections, one warp per row.
// ---------------------------------------------------------------------------
__global__ void k_prep1(const float* __restrict__ img, const float* __restrict__ iW,
                        const float* __restrict__ ib, const float* __restrict__ seq,
                        const float* __restrict__ sW, const float* __restrict__ sb2) {
    int gid = (blockIdx.x * blockDim.x + threadIdx.x) >> 5;
    int lane = threadIdx.x & 31;
    if (gid < B * R) {
        const float* row = img + (size_t)gid * L;
        float s = 0.f;
#pragma unroll
        for (int i = 0; i < L / 32; i++) s += row[lane + 32 * i] * iW[lane + 32 * i];
#pragma unroll
        for (int o = 16; o; o >>= 1) s += __shfl_xor_sync(0xffffffffu, s, o);
        if (lane == 0) g_c[gid] = 1.0f + tanhf(s + ib[0]);
    } else {
        int rq = gid - B * R;   // < B*L by grid sizing
        const float* row = seq + (size_t)rq * K;
        float s = 0.f;
#pragma unroll
        for (int i = 0; i < K / 32; i++) s += row[lane + 32 * i] * sW[lane + 32 * i];
#pragma unroll
        for (int o = 16; o; o >>= 1) s += __shfl_xor_sync(0xffffffffu, s, o);
        if (lane == 0) g_q[rq] = tanhf(s + sb2[0]);
    }
}

// ---------------------------------------------------------------------------
// Kernel 2 (prep2): per-batch  w = q @ V  then masked softmax -> g_S (fp16).
// ---------------------------------------------------------------------------
__global__ __launch_bounds__(512) void k_prep2(const int* __restrict__ mask,
                                               const float* __restrict__ V) {
    const int b = blockIdx.x;
    const int t = threadIdx.x;
    __shared__ float qs[L];
    __shared__ float ws[L];
    __shared__ int ms[L];
    qs[t] = g_q[b * L + t];
    ms[t] = mask[b * L + t];
    __syncthreads();
    float acc = 0.f;
#pragma unroll 8
    for (int l = 0; l < L; l++) acc += qs[l] * V[l * L + t];
    ws[t] = acc;
    __syncthreads();
    const int wid = t >> 5;
    const int lane = t & 31;
    for (int r = wid; r < R; r += 16) {
        float c = g_c[b * R + r];
        float v[L / 32];
        float m = -INFINITY;
#pragma unroll
        for (int i = 0; i < L / 32; i++) {
            int j = lane + 32 * i;
            v[i] = ms[j] ? c * ws[j] : NEGF;
            m = fmaxf(m, v[i]);
        }
#pragma unroll
        for (int o = 16; o; o >>= 1) m = fmaxf(m, __shfl_xor_sync(0xffffffffu, m, o));
        float z = 0.f;
#pragma unroll
        for (int i = 0; i < L / 32; i++) {
            v[i] = __expf(v[i] - m);
            z += v[i];
        }
#pragma unroll
        for (int o = 16; o; o >>= 1) z += __shfl_xor_sync(0xffffffffu, z, o);
        float inv = 1.0f / (z * 27.712812921102035f);   // fold 1/sqrt(768)
        unsigned short* Srow = g_S + ((size_t)(b * R + r)) * L;
#pragma unroll
        for (int i = 0; i < L / 32; i++)
            Srow[lane + 32 * i] = __half_as_ushort(__float2half_rn(v[i] * inv));
    }
}

// ---------------------------------------------------------------------------
// Kernel 3: out[b] = S[b] @ seq_emb[b], fp16 mma.sync m16n8k16, ldmatrix frags.
// BM=128, BN=128, BK=32; 8 warps = 4(M) x 2(N); warp tile 32x64.
// A smem [m][k] pitch 40 halves (LDSM quad stride 5, conflict-free).
// B smem [k][n] pitch 136 halves (LDSM quad stride 17, conflict-free).
// Double-buffered, register prefetch, ONE sync per K-iter, 2 CTAs/SM.
// ---------------------------------------------------------------------------
#define BM 128
#define BN 128
#define BK 32
#define APITCH 40    // halves
#define BPITCH 136   // halves
#define ABUF (BM * APITCH * 2)  // bytes per A buffer = 10240
#define BBUF (BK * BPITCH * 2)  // bytes per B buffer = 8704
#define NIT (L / BK) // 16

__global__ __launch_bounds__(256, 2) void k_gemm_f16(const float* __restrict__ E,
                                                     float* __restrict__ out) {
    const int b = blockIdx.z;
    const int m0 = blockIdx.y * BM;
    const int n0 = blockIdx.x * BN;
    const unsigned short* Sb = g_S + (size_t)b * R * L;
    const float* Eb = E + (size_t)b * L * K + n0;
    float* Ob = out + (size_t)b * R * K;

    __shared__ __align__(16) unsigned short As[2][BM * APITCH];
    __shared__ __align__(16) unsigned short Bs[2][BK * BPITCH];

    const int t = threadIdx.x;
    const int wid = t >> 5;
    const int lane = t & 31;
    const int warp_m = (wid & 3) * 32;
    const int warp_n = (wid >> 2) * 64;
    const int lq = lane >> 2;   // 0..7
    const int lr = lane & 3;    // 0..3

    // loader coordinates
    const int a_row0 = t >> 2, a_c8 = t & 3;   // A: 128 rows x 4 groups of 8 halves
    const int b_kr0 = t >> 5, b_n4 = t & 31;   // B: 32 k-rows x 32 groups of 4 floats

    // ldmatrix lane address bases (bytes)
    const int l8 = lane & 7;
    const int sel = lane >> 3;        // 0..3
    const int selm = sel & 1;         // row-half select
    const int selk = sel >> 1;        // k/n-half select
    const uint32_t sA = smem_u32(&As[0][0]);
    const uint32_t sB = smem_u32(&Bs[0][0]);
    // A: row = warp_m + mi*16 + selm*8 + l8 ; byte = row*80 + ks*32 + selk*16
    const uint32_t aBase = sA + (uint32_t)((warp_m + selm * 8 + l8) * 80 + selk * 16);
    // B: krow = ks*16 + selm*8 + l8 ; nhalf = warp_n + g*16 + selk*8
    const uint32_t bBase = sB + (uint32_t)((selm * 8 + l8) * 272 + (warp_n + selk * 8) * 2);

    float acc[2][8][4];
#pragma unroll
    for (int i = 0; i < 2; i++)
#pragma unroll
        for (int j = 0; j < 8; j++)
#pragma unroll
            for (int k2 = 0; k2 < 4; k2++) acc[i][j][k2] = 0.f;

    uint4 ra[2];
    float4 rb[4];

    // prefetch tile 0
#pragma unroll
    for (int i = 0; i < 2; i++)
        ra[i] = *(const uint4*)&Sb[(size_t)(m0 + a_row0 + i * 64) * L + a_c8 * 8];
#pragma unroll
    for (int i = 0; i < 4; i++)
        rb[i] = *(const float4*)&Eb[(size_t)(b_kr0 + i * 8) * K + b_n4 * 4];
    // store tile 0 -> buffer 0
#pragma unroll
    for (int i = 0; i < 2; i++)
        *(uint4*)&As[0][(a_row0 + i * 64) * APITCH + a_c8 * 8] = ra[i];
#pragma unroll
    for (int i = 0; i < 4; i++) {
        uint2 pk = make_uint2(pack_f2h(rb[i].x, rb[i].y), pack_f2h(rb[i].z, rb[i].w));
        *(uint2*)&Bs[0][(b_kr0 + i * 8) * BPITCH + b_n4 * 4] = pk;
    }
    __syncthreads();

    int buf = 0;
    for (int it = 0; it < NIT; it++) {
        // prefetch next tile into regs (LDGs fly over the mma burst)
        if (it + 1 < NIT) {
            const int k0 = (it + 1) * BK;
#pragma unroll
            for (int i = 0; i < 2; i++)
                ra[i] = *(const uint4*)&Sb[(size_t)(m0 + a_row0 + i * 64) * L + k0 + a_c8 * 8];
#pragma unroll
            for (int i = 0; i < 4; i++)
                rb[i] = *(const float4*)&Eb[(size_t)(k0 + b_kr0 + i * 8) * K + b_n4 * 4];
        }

        // mma burst on buf: 2 k16-steps, fragments via ldmatrix
        const uint32_t aB = aBase + (uint32_t)buf * ABUF;
        const uint32_t bB = bBase + (uint32_t)buf * BBUF;
#pragma unroll
        for (int ks = 0; ks < 2; ks++) {
            uint32_t af[2][4];
#pragma unroll
            for (int mi = 0; mi < 2; mi++) {
                uint32_t addr = aB + (uint32_t)(mi * 16 * 80 + ks * 32);
                asm volatile(
                    "ldmatrix.sync.aligned.m8n8.x4.shared.b16 {%0,%1,%2,%3}, [%4];"
                    : "=r"(af[mi][0]), "=r"(af[mi][1]), "=r"(af[mi][2]), "=r"(af[mi][3])
                    : "r"(addr));
            }
            uint32_t bf[8][2];
#pragma unroll
            for (int g = 0; g < 4; g++) {
                uint32_t addr = bB + (uint32_t)(ks * 16 * 272 + g * 32);
                asm volatile(
                    "ldmatrix.sync.aligned.m8n8.x4.trans.shared.b16 {%0,%1,%2,%3}, [%4];"
                    : "=r"(bf[2 * g][0]), "=r"(bf[2 * g][1]),
                      "=r"(bf[2 * g + 1][0]), "=r"(bf[2 * g + 1][1])
                    : "r"(addr));
            }
#pragma unroll
            for (int mi = 0; mi < 2; mi++)
#pragma unroll
                for (int ni = 0; ni < 8; ni++) {
                    asm volatile(
                        "mma.sync.aligned.m16n8k16.row.col.f32.f16.f16.f32 "
                        "{%0,%1,%2,%3}, {%4,%5,%6,%7}, {%8,%9}, {%0,%1,%2,%3};"
                        : "+f"(acc[mi][ni][0]), "+f"(acc[mi][ni][1]),
                          "+f"(acc[mi][ni][2]), "+f"(acc[mi][ni][3])
                        : "r"(af[mi][0]), "r"(af[mi][1]), "r"(af[mi][2]), "r"(af[mi][3]),
                          "r"(bf[ni][0]), "r"(bf[ni][1]));
                }
        }

        // store prefetched tile into the other buffer (its readers finished
        // at the previous barrier), then ONE sync
        if (it + 1 < NIT) {
            const int nb = buf ^ 1;
#pragma unroll
            for (int i = 0; i < 2; i++)
                *(uint4*)&As[nb][(a_row0 + i * 64) * APITCH + a_c8 * 8] = ra[i];
#pragma unroll
            for (int i = 0; i < 4; i++) {
                uint2 pk = make_uint2(pack_f2h(rb[i].x, rb[i].y),
                                      pack_f2h(rb[i].z, rb[i].w));
                *(uint2*)&Bs[nb][(b_kr0 + i * 8) * BPITCH + b_n4 * 4] = pk;
            }
        }
        __syncthreads();
        buf ^= 1;
    }

    // Epilogue: c0,c1 = (row lq, cols 2lr,2lr+1); c2,c3 = row lq+8
#pragma unroll
    for (int mi = 0; mi < 2; mi++) {
#pragma unroll
        for (int ni = 0; ni < 8; ni++) {
            int gn = n0 + warp_n + ni * 8 + 2 * lr;
            int gm0 = m0 + warp_m + mi * 16 + lq;
            if (gm0 < R) {
                float2 v = make_float2(acc[mi][ni][0], acc[mi][ni][1]);
                *(float2*)&Ob[(size_t)gm0 * K + gn] = v;
            }
            int gm1 = gm0 + 8;
            if (gm1 < R) {
                float2 v = make_float2(acc[mi][ni][2], acc[mi][ni][3]);
                *(float2*)&Ob[(size_t)gm1 * K + gn] = v;
            }
        }
    }
}

// ---------------------------------------------------------------------------
extern "C" void kernel_launch(void* const* d_in, const int* in_sizes, int n_in,
                              void* d_out, int out_size) {
    const float* image_emb = (const float*)d_in[0]; // [B,R,L]
    const float* seq_emb   = (const float*)d_in[1]; // [B,L,K]
    const int*   mask      = (const int*)d_in[2];   // [B,L]
    const float* image_W   = (const float*)d_in[3]; // [L,1]
    const float* image_b   = (const float*)d_in[4]; // [1]
    const float* seq_W     = (const float*)d_in[5]; // [K,1]
    const float* seq_b     = (const float*)d_in[6]; // [1]
    const float* V_weight  = (const float*)d_in[7]; // [L,L]
    float* out = (float*)d_out;                     // [B,R,K]

    // 1) fused projections
    k_prep1<<<(B * R + B * L) / 8, 256>>>(image_emb, image_W, image_b,
                                          seq_emb, seq_W, seq_b);
    // 2) per-batch w + softmax -> fp16 S
    k_prep2<<<B, 512>>>(mask, V_weight);
    // 3) fp16 tensor-core GEMM with ldmatrix fragment loads
    k_gemm_f16<<<dim3(K / BN, (R + BM - 1) / BM, B), 256>>>(seq_emb, out);
}

// round 10
// speedup vs baseline: 1.3818x; 1.0014x over previous
#include <cuda_runtime.h>
#include <cuda_fp16.h>
#include <math.h>
#include <stdint.h>

#define B 64
#define R 196
#define L 512
#define K 768

// ---------------------------------------------------------------------------
// Scratch. g_S holds COMPACTED softmax probs (fp16), zero-padded to a
// multiple of 32 columns; 64 rows of slop for GEMM M-padding.
// ---------------------------------------------------------------------------
__device__ float g_c[B * R];                            // 1 + tanh(image proj)
__device__ float g_q[B * L];                            // tanh(seq proj)
__device__ unsigned short g_S[((size_t)B * R + 64) * L]; // compacted softmax, fp16
__device__ int g_pos[B * L];                            // compacted column index
__device__ int g_cnt[B];                                // padded count (mult of 32)

__device__ __forceinline__ uint32_t pack_f2h(float a, float b) {
    return (uint32_t)__half_as_ushort(__float2half_rn(a)) |
           ((uint32_t)__half_as_ushort(__float2half_rn(b)) << 16);
}
__device__ __forceinline__ uint32_t smem_u32(const void* p) {
    uint32_t a;
    asm("{ .reg .u64 t; cvta.to.shared.u64 t, %1; cvt.u32.u64 %0, t; }"
        : "=r"(a) : "l"(p));
    return a;
}

// ---------------------------------------------------------------------------
// Kernel 1 (prep1): fused p/q projections, one warp per row, float4 loads.
// ---------------------------------------------------------------------------
__global__ void k_prep1(const float* __restrict__ img, const float* __restrict__ iW,
                        const float* __restrict__ ib, const float* __restrict__ seq,
                        const float* __restrict__ sW, const float* __restrict__ sb2) {
    int gid = (blockIdx.x * blockDim.x + threadIdx.x) >> 5;
    int lane = threadIdx.x & 31;
    if (gid < B * R) {
        const float4* row = (const float4*)(img + (size_t)gid * L);
        const float4* W4 = (const float4*)iW;
        float s = 0.f;
#pragma unroll
        for (int i = 0; i < L / 128; i++) {
            float4 a = row[lane + 32 * i], w = W4[lane + 32 * i];
            s += a.x * w.x + a.y * w.y + a.z * w.z + a.w * w.w;
        }
#pragma unroll
        for (int o = 16; o; o >>= 1) s += __shfl_xor_sync(0xffffffffu, s, o);
        if (lane == 0) g_c[gid] = 1.0f + tanhf(s + ib[0]);
    } else {
        int rq = gid - B * R;
        const float4* row = (const float4*)(seq + (size_t)rq * K);
        const float4* W4 = (const float4*)sW;
        float s = 0.f;
#pragma unroll
        for (int i = 0; i < K / 128; i++) {
            float4 a = row[lane + 32 * i], w = W4[lane + 32 * i];
            s += a.x * w.x + a.y * w.y + a.z * w.z + a.w * w.w;
        }
#pragma unroll
        for (int o = 16; o; o >>= 1) s += __shfl_xor_sync(0xffffffffu, s, o);
        if (lane == 0) g_q[rq] = tanhf(s + sb2[0]);
    }
}

// ---------------------------------------------------------------------------
// Kernel 2 (prep2): per-batch w = q@V, mask compaction (ballot scan),
// masked softmax over the compacted list -> g_S fp16 (zero-padded to x32).
// ---------------------------------------------------------------------------
__global__ __launch_bounds__(512) void k_prep2(const int* __restrict__ mask,
                                               const float* __restrict__ V) {
    const int b = blockIdx.x;
    const int t = threadIdx.x;
    const int wid = t >> 5;
    const int lane = t & 31;
    __shared__ float qs[L];
    __shared__ float ws[L];
    __shared__ float wcs[L];          // compacted (w - M)
    __shared__ int posArr[L];
    __shared__ int warpcnt[16];
    __shared__ int warpoff[17];
    __shared__ float warpmax[16];
    __shared__ float Msh;

    qs[t] = g_q[b * L + t];
    int mt = mask[b * L + t];
    uint32_t bal = __ballot_sync(0xffffffffu, mt != 0);
    int inwarp = __popc(bal & ((1u << lane) - 1u));
    if (lane == 0) warpcnt[wid] = __popc(bal);
    __syncthreads();
    if (t == 0) {
        int s = 0;
#pragma unroll
        for (int i = 0; i < 16; i++) { warpoff[i] = s; s += warpcnt[i]; }
        warpoff[16] = s;
    }
    __syncthreads();
    const int cnt = warpoff[16];
    const int cntp = (cnt + 31) & ~31;

    // w[t] = sum_l qs[l] * V[l][t]
    float acc = 0.f;
#pragma unroll 8
    for (int l = 0; l < L; l++) acc += qs[l] * V[l * L + t];
    ws[t] = acc;

    // block max over unmasked w
    float mm = mt ? acc : -INFINITY;
#pragma unroll
    for (int o = 16; o; o >>= 1) mm = fmaxf(mm, __shfl_xor_sync(0xffffffffu, mm, o));
    if (lane == 0) warpmax[wid] = mm;
    if (mt) posArr[warpoff[wid] + inwarp] = t;
    if (t >= cnt && t < cntp) posArr[t] = 0;
    __syncthreads();
    if (t == 0) {
        float M = -INFINITY;
#pragma unroll
        for (int i = 0; i < 16; i++) M = fmaxf(M, warpmax[i]);
        Msh = M;
        g_cnt[b] = cntp;
    }
    __syncthreads();
    const float M = Msh;
    if (t < cntp) {
        wcs[t] = (t < cnt) ? ws[posArr[t]] - M : 0.f;
        g_pos[b * L + t] = posArr[t];
    }
    __syncthreads();

    // softmax rows over compacted list (c > 0 so row max = c*M)
    for (int r = wid; r < R; r += 16) {
        float c = g_c[b * R + r];
        float z = 0.f;
        for (int j = lane; j < cnt; j += 32) z += __expf(c * wcs[j]);
#pragma unroll
        for (int o = 16; o; o >>= 1) z += __shfl_xor_sync(0xffffffffu, z, o);
        float inv = 1.0f / (z * 27.712812921102035f);   // fold 1/sqrt(768)
        unsigned short* Srow = g_S + ((size_t)(b * R + r)) * L;
        for (int j = lane; j < cntp; j += 32) {
            float e = (j < cnt) ? __expf(c * wcs[j]) * inv : 0.f;
            Srow[j] = __half_as_ushort(__float2half_rn(e));
        }
    }
}

// ---------------------------------------------------------------------------
// Kernel 3: out[b] = S_compact[b] @ gather(E[b], pos[b]); fp16 mma + ldmatrix.
// Dynamic K-extent cntp[b] (~256+pad instead of 512) -> ~2x fewer MMAs.
// ---------------------------------------------------------------------------
#define BM 128
#define BN 128
#define BK 32
#define APITCH 40    // halves
#define BPITCH 136   // halves
#define ABUF (BM * APITCH * 2)
#define BBUF (BK * BPITCH * 2)

__global__ __launch_bounds__(256, 2) void k_gemm_f16(const float* __restrict__ E,
                                                     float* __restrict__ out) {
    const int b = blockIdx.z;
    const int m0 = blockIdx.y * BM;
    const int n0 = blockIdx.x * BN;
    const unsigned short* Sb = g_S + (size_t)b * R * L;
    const float* Eb = E + (size_t)b * L * K + n0;
    float* Ob = out + (size_t)b * R * K;

    __shared__ __align__(16) unsigned short As[2][BM * APITCH];
    __shared__ __align__(16) unsigned short Bs[2][BK * BPITCH];
    __shared__ int posS[L];

    const int t = threadIdx.x;
    const int wid = t >> 5;
    const int lane = t & 31;
    const int warp_m = (wid & 3) * 32;
    const int warp_n = (wid >> 2) * 64;
    const int lq = lane >> 2;
    const int lr = lane & 3;

    const int nit = g_cnt[b] >> 5;   // dynamic K-iterations

    const int a_row0 = t >> 2, a_c8 = t & 3;
    const int b_kr0 = t >> 5, b_n4 = t & 31;

    const int l8 = lane & 7;
    const int sel = lane >> 3;
    const int selm = sel & 1;
    const int selk = sel >> 1;
    const uint32_t sA = smem_u32(&As[0][0]);
    const uint32_t sB = smem_u32(&Bs[0][0]);
    const uint32_t aBase = sA + (uint32_t)((warp_m + selm * 8 + l8) * 80 + selk * 16);
    const uint32_t bBase = sB + (uint32_t)((selm * 8 + l8) * 272 + (warp_n + selk * 8) * 2);

    // load compacted position list
    posS[t] = g_pos[b * L + t];
    posS[t + 256] = g_pos[b * L + t + 256];
    __syncthreads();

    float acc[2][8][4];
#pragma unroll
    for (int i = 0; i < 2; i++)
#pragma unroll
        for (int j = 0; j < 8; j++)
#pragma unroll
            for (int k2 = 0; k2 < 4; k2++) acc[i][j][k2] = 0.f;

    uint4 ra[2];
    float4 rb[4];

    // prefetch tile 0 (B rows gathered via posS; whole warp shares one row)
#pragma unroll
    for (int i = 0; i < 2; i++)
        ra[i] = *(const uint4*)&Sb[(size_t)(m0 + a_row0 + i * 64) * L + a_c8 * 8];
#pragma unroll
    for (int i = 0; i < 4; i++)
        rb[i] = *(const float4*)&Eb[(size_t)posS[b_kr0 + i * 8] * K + b_n4 * 4];
#pragma unroll
    for (int i = 0; i < 2; i++)
        *(uint4*)&As[0][(a_row0 + i * 64) * APITCH + a_c8 * 8] = ra[i];
#pragma unroll
    for (int i = 0; i < 4; i++) {
        uint2 pk = make_uint2(pack_f2h(rb[i].x, rb[i].y), pack_f2h(rb[i].z, rb[i].w));
        *(uint2*)&Bs[0][(b_kr0 + i * 8) * BPITCH + b_n4 * 4] = pk;
    }
    __syncthreads();

    int buf = 0;
    for (int it = 0; it < nit; it++) {
        if (it + 1 < nit) {
            const int k0 = (it + 1) * BK;
#pragma unroll
            for (int i = 0; i < 2; i++)
                ra[i] = *(const uint4*)&Sb[(size_t)(m0 + a_row0 + i * 64) * L + k0 + a_c8 * 8];
#pragma unroll
            for (int i = 0; i < 4; i++)
                rb[i] = *(const float4*)&Eb[(size_t)posS[k0 + b_kr0 + i * 8] * K + b_n4 * 4];
        }

        const uint32_t aB = aBase + (uint32_t)buf * ABUF;
        const uint32_t bB = bBase + (uint32_t)buf * BBUF;
#pragma unroll
        for (int ks = 0; ks < 2; ks++) {
            uint32_t af[2][4];
#pragma unroll
            for (int mi = 0; mi < 2; mi++) {
                uint32_t addr = aB + (uint32_t)(mi * 16 * 80 + ks * 32);
                asm volatile(
                    "ldmatrix.sync.aligned.m8n8.x4.shared.b16 {%0,%1,%2,%3}, [%4];"
                    : "=r"(af[mi][0]), "=r"(af[mi][1]), "=r"(af[mi][2]), "=r"(af[mi][3])
                    : "r"(addr));
            }
            uint32_t bf[8][2];
#pragma unroll
            for (int g = 0; g < 4; g++) {
                uint32_t addr = bB + (uint32_t)(ks * 16 * 272 + g * 32);
                asm volatile(
                    "ldmatrix.sync.aligned.m8n8.x4.trans.shared.b16 {%0,%1,%2,%3}, [%4];"
                    : "=r"(bf[2 * g][0]), "=r"(bf[2 * g][1]),
                      "=r"(bf[2 * g + 1][0]), "=r"(bf[2 * g + 1][1])
                    : "r"(addr));
            }
#pragma unroll
            for (int mi = 0; mi < 2; mi++)
#pragma unroll
                for (int ni = 0; ni < 8; ni++) {
                    asm volatile(
                        "mma.sync.aligned.m16n8k16.row.col.f32.f16.f16.f32 "
                        "{%0,%1,%2,%3}, {%4,%5,%6,%7}, {%8,%9}, {%0,%1,%2,%3};"
                        : "+f"(acc[mi][ni][0]), "+f"(acc[mi][ni][1]),
                          "+f"(acc[mi][ni][2]), "+f"(acc[mi][ni][3])
                        : "r"(af[mi][0]), "r"(af[mi][1]), "r"(af[mi][2]), "r"(af[mi][3]),
                          "r"(bf[ni][0]), "r"(bf[ni][1]));
                }
        }

        if (it + 1 < nit) {
            const int nb = buf ^ 1;
#pragma unroll
            for (int i = 0; i < 2; i++)
                *(uint4*)&As[nb][(a_row0 + i * 64) * APITCH + a_c8 * 8] = ra[i];
#pragma unroll
            for (int i = 0; i < 4; i++) {
                uint2 pk = make_uint2(pack_f2h(rb[i].x, rb[i].y),
                                      pack_f2h(rb[i].z, rb[i].w));
                *(uint2*)&Bs[nb][(b_kr0 + i * 8) * BPITCH + b_n4 * 4] = pk;
            }
        }
        __syncthreads();
        buf ^= 1;
    }

    // Epilogue
#pragma unroll
    for (int mi = 0; mi < 2; mi++) {
#pragma unroll
        for (int ni = 0; ni < 8; ni++) {
            int gn = n0 + warp_n + ni * 8 + 2 * lr;
            int gm0 = m0 + warp_m + mi * 16 + lq;
            if (gm0 < R) {
                float2 v = make_float2(acc[mi][ni][0], acc[mi][ni][1]);
                *(float2*)&Ob[(size_t)gm0 * K + gn] = v;
            }
            int gm1 = gm0 + 8;
            if (gm1 < R) {
                float2 v = make_float2(acc[mi][ni][2], acc[mi][ni][3]);
                *(float2*)&Ob[(size_t)gm1 * K + gn] = v;
            }
        }
    }
}

// ---------------------------------------------------------------------------
extern "C" void kernel_launch(void* const* d_in, const int* in_sizes, int n_in,
                              void* d_out, int out_size) {
    const float* image_emb = (const float*)d_in[0]; // [B,R,L]
    const float* seq_emb   = (const float*)d_in[1]; // [B,L,K]
    const int*   mask      = (const int*)d_in[2];   // [B,L]
    const float* image_W   = (const float*)d_in[3]; // [L,1]
    const float* image_b   = (const float*)d_in[4]; // [1]
    const float* seq_W     = (const float*)d_in[5]; // [K,1]
    const float* seq_b     = (const float*)d_in[6]; // [1]
    const float* V_weight  = (const float*)d_in[7]; // [L,L]
    float* out = (float*)d_out;                     // [B,R,K]

    k_prep1<<<(B * R + B * L) / 8, 256>>>(image_emb, image_W, image_b,
                                          seq_emb, seq_W, seq_b);
    k_prep2<<<B, 512>>>(mask, V_weight);
    k_gemm_f16<<<dim3(K / BN, (R + BM - 1) / BM, B), 256>>>(seq_emb, out);
}

// round 12
// speedup vs baseline: 1.7572x; 1.2717x over previous
#include <cuda_runtime.h>
#include <cuda_fp16.h>
#include <math.h>
#include <stdint.h>

#define B 64
#define R 196
#define L 512
#define K 768

// ---------------------------------------------------------------------------
// Scratch (no cudaMalloc allowed).
// ---------------------------------------------------------------------------
__device__ float g_c[B * R];                             // 1 + tanh(image proj)
__device__ float g_q[B * L];                             // tanh(seq proj)
__device__ float g_wc[B * L];                            // compacted (w - M)
__device__ unsigned short g_S[((size_t)B * R + 64) * L]; // compacted softmax, fp16
__device__ unsigned short g_Eh[(size_t)B * L * K];       // seq_emb in fp16
__device__ int g_pos[B * L];                             // compacted column index
__device__ int g_cnt[B * 2];                             // [2b]=cnt, [2b+1]=cntp

__device__ __forceinline__ uint32_t pack_f2h(float a, float b) {
    return (uint32_t)__half_as_ushort(__float2half_rn(a)) |
           ((uint32_t)__half_as_ushort(__float2half_rn(b)) << 16);
}
__device__ __forceinline__ uint32_t smem_u32(const void* p) {
    uint32_t a;
    asm("{ .reg .u64 t; cvta.to.shared.u64 t, %1; cvt.u32.u64 %0, t; }"
        : "=r"(a) : "l"(p));
    return a;
}

// ---------------------------------------------------------------------------
// Kernel 1 (prep1): fused p/q projections + fp16 transcode of seq_emb.
// ---------------------------------------------------------------------------
__global__ void k_prep1(const float* __restrict__ img, const float* __restrict__ iW,
                        const float* __restrict__ ib, const float* __restrict__ seq,
                        const float* __restrict__ sW, const float* __restrict__ sb2) {
    int gid = (blockIdx.x * blockDim.x + threadIdx.x) >> 5;
    int lane = threadIdx.x & 31;
    if (gid < B * R) {
        const float4* row = (const float4*)(img + (size_t)gid * L);
        const float4* W4 = (const float4*)iW;
        float s = 0.f;
#pragma unroll
        for (int i = 0; i < L / 128; i++) {
            float4 a = row[lane + 32 * i], w = W4[lane + 32 * i];
            s += a.x * w.x + a.y * w.y + a.z * w.z + a.w * w.w;
        }
#pragma unroll
        for (int o = 16; o; o >>= 1) s += __shfl_xor_sync(0xffffffffu, s, o);
        if (lane == 0) g_c[gid] = 1.0f + tanhf(s + ib[0]);
    } else {
        int rq = gid - B * R;
        const float4* row = (const float4*)(seq + (size_t)rq * K);
        const float4* W4 = (const float4*)sW;
        uint2* eh = (uint2*)(g_Eh + (size_t)rq * K);
        float s = 0.f;
#pragma unroll
        for (int i = 0; i < K / 128; i++) {
            float4 a = row[lane + 32 * i], w = W4[lane + 32 * i];
            s += a.x * w.x + a.y * w.y + a.z * w.z + a.w * w.w;
            eh[lane + 32 * i] = make_uint2(pack_f2h(a.x, a.y), pack_f2h(a.z, a.w));
        }
#pragma unroll
        for (int o = 16; o; o >>= 1) s += __shfl_xor_sync(0xffffffffu, s, o);
        if (lane == 0) g_q[rq] = tanhf(s + sb2[0]);
    }
}

// ---------------------------------------------------------------------------
// Kernel 2a: per-batch w = q@V, ballot compaction -> g_wc, g_pos, g_cnt.
// ---------------------------------------------------------------------------
__global__ __launch_bounds__(512) void k_prep2a(const int* __restrict__ mask,
                                                const float* __restrict__ V) {
    const int b = blockIdx.x;
    const int t = threadIdx.x;
    const int wid = t >> 5;
    const int lane = t & 31;
    __shared__ float qs[L];
    __shared__ float ws[L];
    __shared__ int posArr[L];
    __shared__ int warpcnt[16];
    __shared__ int warpoff[17];
    __shared__ float warpmax[16];
    __shared__ float Msh;

    qs[t] = g_q[b * L + t];
    int mt = mask[b * L + t];
    uint32_t bal = __ballot_sync(0xffffffffu, mt != 0);
    int inwarp = __popc(bal & ((1u << lane) - 1u));
    if (lane == 0) warpcnt[wid] = __popc(bal);
    __syncthreads();
    if (t == 0) {
        int s = 0;
#pragma unroll
        for (int i = 0; i < 16; i++) { warpoff[i] = s; s += warpcnt[i]; }
        warpoff[16] = s;
    }
    __syncthreads();
    const int cnt = warpoff[16];
    const int cntp = (cnt + 31) & ~31;

    float acc = 0.f;
#pragma unroll 8
    for (int l = 0; l < L; l++) acc += qs[l] * V[l * L + t];
    ws[t] = acc;

    float mm = mt ? acc : -INFINITY;
#pragma unroll
    for (int o = 16; o; o >>= 1) mm = fmaxf(mm, __shfl_xor_sync(0xffffffffu, mm, o));
    if (lane == 0) warpmax[wid] = mm;
    if (mt) posArr[warpoff[wid] + inwarp] = t;
    if (t >= cnt && t < cntp) posArr[t] = 0;
    __syncthreads();
    if (t == 0) {
        float M = -INFINITY;
#pragma unroll
        for (int i = 0; i < 16; i++) M = fmaxf(M, warpmax[i]);
        Msh = M;
        g_cnt[2 * b] = cnt;
        g_cnt[2 * b + 1] = cntp;
    }
    __syncthreads();
    if (t < cntp) {
        g_wc[b * L + t] = (t < cnt) ? ws[posArr[t]] - Msh : 0.f;
        g_pos[b * L + t] = posArr[t];
    }
}

// ---------------------------------------------------------------------------
// Kernel 2b: softmax rows over compacted list -> g_S fp16 (exp computed once).
// ---------------------------------------------------------------------------
__global__ __launch_bounds__(256) void k_prep2b() {
    const int b = blockIdx.x;
    const int t = threadIdx.x;
    const int wid = t >> 5;
    const int lane = t & 31;
    __shared__ float wcs[L];
    __shared__ int cntS[2];
    if (t < 2) cntS[t] = g_cnt[2 * b + t];
    __syncthreads();
    const int cnt = cntS[0];
    const int cntp = cntS[1];
    for (int j = t; j < cntp; j += 256) wcs[j] = g_wc[b * L + j];
    __syncthreads();

    const int r = blockIdx.y * 8 + wid;
    if (r >= R) return;
    const float c = g_c[b * R + r];
    float e[16];
    float z = 0.f;
#pragma unroll
    for (int i = 0; i < 16; i++) {
        int j = lane + 32 * i;
        if (j < cnt) {
            e[i] = __expf(c * wcs[j]);
            z += e[i];
        } else e[i] = 0.f;
    }
#pragma unroll
    for (int o = 16; o; o >>= 1) z += __shfl_xor_sync(0xffffffffu, z, o);
    const float inv = 1.0f / (z * 27.712812921102035f);   // fold 1/sqrt(768)
    unsigned short* Srow = g_S + ((size_t)(b * R + r)) * L;
#pragma unroll
    for (int i = 0; i < 16; i++) {
        int j = lane + 32 * i;
        if (j < cntp)
            Srow[j] = __half_as_ushort(__float2half_rn(e[i] * inv));
    }
}

// ---------------------------------------------------------------------------
// Kernel 3: out[b] = S_compact[b] @ gather(Eh[b], pos[b]); fp16 mma + ldmatrix.
// ---------------------------------------------------------------------------
#define BM 128
#define BN 128
#define BK 32
#define APITCH 40    // halves
#define BPITCH 136   // halves
#define ABUF (BM * APITCH * 2)
#define BBUF (BK * BPITCH * 2)

__global__ __launch_bounds__(256, 2) void k_gemm_f16(float* __restrict__ out) {
    const int b = blockIdx.z;
    const int m0 = blockIdx.y * BM;
    const int n0 = blockIdx.x * BN;
    const unsigned short* Sb = g_S + (size_t)b * R * L;
    const unsigned short* Eb = g_Eh + (size_t)b * L * K + n0;
    float* Ob = out + (size_t)b * R * K;

    __shared__ __align__(16) unsigned short As[2][BM * APITCH];
    __shared__ __align__(16) unsigned short Bs[2][BK * BPITCH];
    __shared__ int posS[L];

    const int t = threadIdx.x;
    const int wid = t >> 5;
    const int lane = t & 31;
    const int warp_m = (wid & 3) * 32;
    const int warp_n = (wid >> 2) * 64;
    const int lq = lane >> 2;
    const int lr = lane & 3;

    const int nit = g_cnt[2 * b + 1] >> 5;   // dynamic K-iterations

    const int a_row0 = t >> 2, a_c8 = t & 3;   // A: 2 uint4/thread (rows +64)
    const int b_kr0 = t >> 4, b_n8 = t & 15;   // B: 2 uint4/thread (rows +16)

    const int l8 = lane & 7;
    const int sel = lane >> 3;
    const int selm = sel & 1;
    const int selk = sel >> 1;
    const uint32_t sA = smem_u32(&As[0][0]);
    const uint32_t sB = smem_u32(&Bs[0][0]);
    const uint32_t aBase = sA + (uint32_t)((warp_m + selm * 8 + l8) * 80 + selk * 16);
    const uint32_t bBase = sB + (uint32_t)((selm * 8 + l8) * 272 + (warp_n + selk * 8) * 2);

    posS[t] = g_pos[b * L + t];
    posS[t + 256] = g_pos[b * L + t + 256];
    __syncthreads();

    float acc[2][8][4];
#pragma unroll
    for (int i = 0; i < 2; i++)
#pragma unroll
        for (int j = 0; j < 8; j++)
#pragma unroll
            for (int k2 = 0; k2 < 4; k2++) acc[i][j][k2] = 0.f;

    uint4 ra[2], rb[2];

    // prefetch tile 0
#pragma unroll
    for (int i = 0; i < 2; i++)
        ra[i] = *(const uint4*)&Sb[(size_t)(m0 + a_row0 + i * 64) * L + a_c8 * 8];
#pragma unroll
    for (int i = 0; i < 2; i++)
        rb[i] = *(const uint4*)&Eb[(size_t)posS[b_kr0 + i * 16] * K + b_n8 * 8];
#pragma unroll
    for (int i = 0; i < 2; i++)
        *(uint4*)&As[0][(a_row0 + i * 64) * APITCH + a_c8 * 8] = ra[i];
#pragma unroll
    for (int i = 0; i < 2; i++)
        *(uint4*)&Bs[0][(b_kr0 + i * 16) * BPITCH + b_n8 * 8] = rb[i];
    __syncthreads();

    int buf = 0;
    for (int it = 0; it < nit; it++) {
        if (it + 1 < nit) {
            const int k0 = (it + 1) * BK;
#pragma unroll
            for (int i = 0; i < 2; i++)
                ra[i] = *(const uint4*)&Sb[(size_t)(m0 + a_row0 + i * 64) * L + k0 + a_c8 * 8];
#pragma unroll
            for (int i = 0; i < 2; i++)
                rb[i] = *(const uint4*)&Eb[(size_t)posS[k0 + b_kr0 + i * 16] * K + b_n8 * 8];
        }

        const uint32_t aB = aBase + (uint32_t)buf * ABUF;
        const uint32_t bB = bBase + (uint32_t)buf * BBUF;
#pragma unroll
        for (int ks = 0; ks < 2; ks++) {
            uint32_t af[2][4];
#pragma unroll
            for (int mi = 0; mi < 2; mi++) {
                uint32_t addr = aB + (uint32_t)(mi * 16 * 80 + ks * 32);
                asm volatile(
                    "ldmatrix.sync.aligned.m8n8.x4.shared.b16 {%0,%1,%2,%3}, [%4];"
                    : "=r"(af[mi][0]), "=r"(af[mi][1]), "=r"(af[mi][2]), "=r"(af[mi][3])
                    : "r"(addr));
            }
            uint32_t bf[8][2];
#pragma unroll
            for (int g = 0; g < 4; g++) {
                uint32_t addr = bB + (uint32_t)(ks * 16 * 272 + g * 32);
                asm volatile(
                    "ldmatrix.sync.aligned.m8n8.x4.trans.shared.b16 {%0,%1,%2,%3}, [%4];"
                    : "=r"(bf[2 * g][0]), "=r"(bf[2 * g][1]),
                      "=r"(bf[2 * g + 1][0]), "=r"(bf[2 * g + 1][1])
                    : "r"(addr));
            }
#pragma unroll
            for (int mi = 0; mi < 2; mi++)
#pragma unroll
                for (int ni = 0; ni < 8; ni++) {
                    asm volatile(
                        "mma.sync.aligned.m16n8k16.row.col.f32.f16.f16.f32 "
                        "{%0,%1,%2,%3}, {%4,%5,%6,%7}, {%8,%9}, {%0,%1,%2,%3};"
                        : "+f"(acc[mi][ni][0]), "+f"(acc[mi][ni][1]),
                          "+f"(acc[mi][ni][2]), "+f"(acc[mi][ni][3])
                        : "r"(af[mi][0]), "r"(af[mi][1]), "r"(af[mi][2]), "r"(af[mi][3]),
                          "r"(bf[ni][0]), "r"(bf[ni][1]));
                }
        }

        if (it + 1 < nit) {
            const int nb = buf ^ 1;
#pragma unroll
            for (int i = 0; i < 2; i++)
                *(uint4*)&As[nb][(a_row0 + i * 64) * APITCH + a_c8 * 8] = ra[i];
#pragma unroll
            for (int i = 0; i < 2; i++)
                *(uint4*)&Bs[nb][(b_kr0 + i * 16) * BPITCH + b_n8 * 8] = rb[i];
        }
        __syncthreads();
        buf ^= 1;
    }

    // Epilogue
#pragma unroll
    for (int mi = 0; mi < 2; mi++) {
#pragma unroll
        for (int ni = 0; ni < 8; ni++) {
            int gn = n0 + warp_n + ni * 8 + 2 * lr;
            int gm0 = m0 + warp_m + mi * 16 + lq;
            if (gm0 < R) {
                float2 v = make_float2(acc[mi][ni][0], acc[mi][ni][1]);
                *(float2*)&Ob[(size_t)gm0 * K + gn] = v;
            }
            int gm1 = gm0 + 8;
            if (gm1 < R) {
                float2 v = make_float2(acc[mi][ni][2], acc[mi][ni][3]);
                *(float2*)&Ob[(size_t)gm1 * K + gn] = v;
            }
        }
    }
}

// ---------------------------------------------------------------------------
extern "C" void kernel_launch(void* const* d_in, const int* in_sizes, int n_in,
                              void* d_out, int out_size) {
    const float* image_emb = (const float*)d_in[0]; // [B,R,L]
    const float* seq_emb   = (const float*)d_in[1]; // [B,L,K]
    const int*   mask      = (const int*)d_in[2];   // [B,L]
    const float* image_W   = (const float*)d_in[3]; // [L,1]
    const float* image_b   = (const float*)d_in[4]; // [1]
    const float* seq_W     = (const float*)d_in[5]; // [K,1]
    const float* seq_b     = (const float*)d_in[6]; // [1]
    const float* V_weight  = (const float*)d_in[7]; // [L,L]
    float* out = (float*)d_out;                     // [B,R,K]

    k_prep1<<<(B * R + B * L) / 8, 256>>>(image_emb, image_W, image_b,
                                          seq_emb, seq_W, seq_b);
    k_prep2a<<<B, 512>>>(mask, V_weight);
    k_prep2b<<<dim3(B, 25), 256>>>();
    k_gemm_f16<<<dim3(K / BN, (R + BM - 1) / BM, B), 256>>>(out);
}